// round 12
// baseline (speedup 1.0000x reference)
#include <cuda_runtime.h>
#include <math_constants.h>
#include <cstdint>

// Problem: B=128, L=4096, FILTER_SIZE=2, N_QUBITS=4, 10 classes.
// Analytic reduction: expval_k(b,ol) = K_k * g(b,ol),
//   K_k = cos(p_k1)cos(p_k2)cos(p_k3)   (CNOT ring conjugates Z0 -> Z1Z2Z3)
//   g   = cos(x[ol,1]) * cos(x[ol+1,0]) * cos(x[ol+1,1])
// logits[j] = bias[j] + sum_ol g(ol)*(K0*W[2ol,j]+K1*W[2ol+1,j]); softmax.
//
// SPLIT-K: block k owns windows [32k,32k+32) for ALL rows. It folds only its
// own 64 W rows (no cross-block weight broadcast / dependency), accumulates
// per-row partial logits via atomicAdd, and the last block does the softmax.
#define OLP   4096
#define NCLS  10
#define B_SZ  128
#define NT    512
#define W_F4  20475          // float4 count of W (8190*10 floats)
#define WSTR  12             // floats per window row in wf (16B-aligned rows)
#define CSTR  492            // floats per s-copy; s-coeff 588%32=12 -> banks {0,12,24,4}

__device__ float d_logits[B_SZ * NCLS];   // zero at load; self-cleaned each call
__device__ int   d_fin;

__global__ __launch_bounds__(NT, 1)
void qcnn_splitk(const float* __restrict__ x, const float* __restrict__ params,
                 const float* __restrict__ W, const float* __restrict__ bias,
                 float* __restrict__ out)
{
    __shared__ __align__(16) float sw[640];                    // raw W slice
    __shared__ __align__(16) float wf[3 * CSTR + 31 * WSTR + NCLS + 2];
    __shared__ int s_last;

    const int k   = blockIdx.x;          // window chunk [32k, 32k+32)
    const int tid = threadIdx.x;
    const int row = tid >> 2;            // 0..127
    const int s   = tid & 3;             // 8-window subchunk within the chunk

    // ---- x loads first (pairs p0..p0+8), overlap W staging + fold
    const float* xr  = x + (size_t)row * (OLP * 2);
    const float4* xr4 = (const float4*)xr;
    const int p0 = 32 * k + 8 * s;
    float4 a0 = xr4[(p0 >> 1)    ];      // pairs p0,   p0+1
    float4 a1 = xr4[(p0 >> 1) + 1];      // pairs p0+2, p0+3
    float4 a2 = xr4[(p0 >> 1) + 2];      // pairs p0+4, p0+5
    float4 a3 = xr4[(p0 >> 1) + 3];      // pairs p0+6, p0+7
    const int p8 = p0 + 8;
    float2 a4 = *(const float2*)(xr + ((p8 >= OLP) ? 0 : 2 * p8));  // pair p0+8

    // ---- stage this block's raw W rows [64k, 64k+64) = f4 [160k, 160k+160)
    if (tid < 160) {
        int gi = 160 * k + tid;
        ((float4*)sw)[tid] = (gi < W_F4) ? ((const float4*)W)[gi]
                                         : make_float4(0.f, 0.f, 0.f, 0.f);
    }
    __syncthreads();

    // ---- fold into 4 replicated smem copies (per s-group, conflict-free)
    if (tid < 128) {
        float K0 = __cosf(params[1]) * __cosf(params[2]) * __cosf(params[3]);
        float K1 = __cosf(params[5]) * __cosf(params[6]) * __cosf(params[7]);
        int c = tid >> 5, ol = tid & 31;            // copy, local window
        const float* r = &sw[20 * ol];              // rows 2ol, 2ol+1
        float* dst = &wf[c * CSTR + ol * WSTR];
#pragma unroll
        for (int j = 0; j < NCLS; ++j)
            dst[j] = fmaf(K1, r[10 + j], K0 * r[j]);
    }
    __syncthreads();

    // ---- cos products: s1[i]=cos(x1_i); h[i]=cos(x0_i)*s1[i]; g[i]=s1[i]*h[i+1]
    float s1[8], h9[9];
    {
        float c;
        s1[0] = __cosf(a0.y);
        c = __cosf(a0.w); s1[1] = c; h9[1] = __cosf(a0.z) * c;
        c = __cosf(a1.y); s1[2] = c; h9[2] = __cosf(a1.x) * c;
        c = __cosf(a1.w); s1[3] = c; h9[3] = __cosf(a1.z) * c;
        c = __cosf(a2.y); s1[4] = c; h9[4] = __cosf(a2.x) * c;
        c = __cosf(a2.w); s1[5] = c; h9[5] = __cosf(a2.z) * c;
        c = __cosf(a3.y); s1[6] = c; h9[6] = __cosf(a3.x) * c;
        c = __cosf(a3.w); s1[7] = c; h9[7] = __cosf(a3.z) * c;
        h9[8] = __cosf(a4.x) * __cosf(a4.y);
    }
    float g[8];
#pragma unroll
    for (int i = 0; i < 8; ++i) g[i] = s1[i] * h9[i + 1];
    // padded window 4095 (k=127,s=3,i=7): its folded weights are 0 (OOB guard)

    // ---- 8 windows x 10 classes; weight reads are bank-conflict-free LDS
    float acc[NCLS];
#pragma unroll
    for (int j = 0; j < NCLS; ++j) acc[j] = 0.f;
    const float* wbase = &wf[s * CSTR + (8 * s) * WSTR];   // = wf + 588*s
#pragma unroll
    for (int i = 0; i < 8; ++i) {
        const float* wr = wbase + i * WSTR;
        float4 w0 = *(const float4*)wr;
        float4 w1 = *(const float4*)(wr + 4);
        float2 w2 = *(const float2*)(wr + 8);
        float gi = g[i];
        acc[0] = fmaf(gi, w0.x, acc[0]);
        acc[1] = fmaf(gi, w0.y, acc[1]);
        acc[2] = fmaf(gi, w0.z, acc[2]);
        acc[3] = fmaf(gi, w0.w, acc[3]);
        acc[4] = fmaf(gi, w1.x, acc[4]);
        acc[5] = fmaf(gi, w1.y, acc[5]);
        acc[6] = fmaf(gi, w1.z, acc[6]);
        acc[7] = fmaf(gi, w1.w, acc[7]);
        acc[8] = fmaf(gi, w2.x, acc[8]);
        acc[9] = fmaf(gi, w2.y, acc[9]);
    }

    // ---- combine the 4 s-lanes of each row (lanes 4r..4r+3), then atomics
#pragma unroll
    for (int j = 0; j < NCLS; ++j) {
        acc[j] += __shfl_xor_sync(0xFFFFFFFFu, acc[j], 1);
        acc[j] += __shfl_xor_sync(0xFFFFFFFFu, acc[j], 2);
    }
    if (s == 0) {
#pragma unroll
        for (int j = 0; j < NCLS; ++j)
            atomicAdd(&d_logits[row * NCLS + j], acc[j]);
        __threadfence();
    }
    __syncthreads();

    // ---- single ticket; ONLY the last block proceeds (nobody ever polls)
    if (tid == 0) s_last = (atomicAdd(&d_fin, 1) == B_SZ - 1);
    __syncthreads();
    if (!s_last) return;

    // ---- last block: bias + softmax for all 128 rows, then self-clean
    if (tid < B_SZ) {
        float l[NCLS];
#pragma unroll
        for (int j = 0; j < NCLS; ++j)      // atomic read => L2-coherent
            l[j] = atomicAdd(&d_logits[tid * NCLS + j], 0.f) + bias[j];
        float mx = l[0];
#pragma unroll
        for (int j = 1; j < NCLS; ++j) mx = fmaxf(mx, l[j]);
        float sum = 0.f;
#pragma unroll
        for (int j = 0; j < NCLS; ++j) { l[j] = __expf(l[j] - mx); sum += l[j]; }
        float inv = __frcp_rn(sum);
#pragma unroll
        for (int j = 0; j < NCLS; ++j)
            out[tid * NCLS + j] = l[j] * inv;
    }
    __syncthreads();
    for (int i = tid; i < B_SZ * NCLS; i += NT) d_logits[i] = 0.f;  // replay-safe
    if (tid == 0) { d_fin = 0; __threadfence(); }
}

// Inputs (metadata order): inputs(128*4096*2 f32), params(8 f32),
//                          W(8190*10 f32), b(10 f32). Output: (128*10) f32.
extern "C" void kernel_launch(void* const* d_in, const int* in_sizes, int n_in,
                              void* d_out, int out_size)
{
    const float* inputs = (const float*)d_in[0];
    const float* params = (const float*)d_in[1];
    const float* W      = (const float*)d_in[2];
    const float* bias   = (const float*)d_in[3];
    float* out          = (float*)d_out;

    qcnn_splitk<<<B_SZ, NT>>>(inputs, params, W, bias, out);
}

// round 13
// speedup vs baseline: 1.9574x; 1.9574x over previous
#include <cuda_runtime.h>
#include <math_constants.h>
#include <cstdint>

// Problem: B=128, L=4096, FILTER_SIZE=2, N_QUBITS=4, 10 classes.
// Analytic reduction: expval_k(b,ol) = K_k * g(b,ol),
//   K_k = cos(p_k1)cos(p_k2)cos(p_k3)   (CNOT ring conjugates Z0 -> Z1Z2Z3)
//   g   = cos(x[ol,1]) * cos(x[ol+1,0]) * cos(x[ol+1,1])
// logits[j] = bias[j] + sum_ol g(ol)*(K0*W[2ol,j]+K1*W[2ol+1,j]); softmax.
#define OLP    4096
#define NCLS   10
#define B_SZ   128
#define NT     1024
#define HWIN   2048           // windows per block (half row)
#define W_F4   20475          // float4 count of W (8190*10 floats)

// Folded, TRANSPOSED weights d_Wp[j*OLP + ol]; column 4095 is zero (pad).
__device__ __align__(16) float d_Wp[NCLS * OLP];
// Cross-block (two halves per row) combine scratch; zero at load, and each
// call leaves it zero again (self-cleaning) so graph replays are correct.
__device__ float d_logits[B_SZ * NCLS];
__device__ int   d_tick[B_SZ];

// ---------------------------------------------------------------------------
// Prep: fold+transpose W into d_Wp. 32 blocks x 256 threads (R4-proven).
// ---------------------------------------------------------------------------
__global__ __launch_bounds__(256) void qcnn_prep(const float* __restrict__ params,
                                                 const float* __restrict__ W)
{
    __shared__ float sw[2560];
    const int bid = blockIdx.x, tid = threadIdx.x;

    const float4* w4 = (const float4*)W;
    const int f4base = bid * 640;
#pragma unroll
    for (int k = 0; k < 3; ++k) {
        int li = tid + k * 256;
        if (li < 640) {
            int gi = f4base + li;
            float4 v = (gi < W_F4) ? w4[gi] : make_float4(0.f, 0.f, 0.f, 0.f);
            *(float4*)&sw[4 * li] = v;
        }
    }
    __syncthreads();

    if (tid < 128) {
        float K0 = __cosf(params[1]) * __cosf(params[2]) * __cosf(params[3]);
        float K1 = __cosf(params[5]) * __cosf(params[6]) * __cosf(params[7]);
        int ol = bid * 128 + tid;
        const float* r = &sw[20 * tid];          // rows 2ol, 2ol+1 (10 f each)
#pragma unroll
        for (int j = 0; j < NCLS; ++j)
            d_Wp[j * OLP + ol] = fmaf(K1, r[10 + j], K0 * r[j]);
    }
}

// ---------------------------------------------------------------------------
// Main: 128 blocks = 64 row-pairs x 2 window-halves; 1024 threads.
// Warps 0-15 -> row 2rg, warps 16-31 -> row 2rg+1. Both rows read the SAME
// 80KB Wp chunk via plain LDG.128: first reader pays L2, second hits L1.
// Thread tp of half h owns windows 2048h+4tp..+3 (x f4 idx 1024h+2tp,
// Wp f4 idx 512h+tp). No staging, no wait-group: warps stay independent.
// ---------------------------------------------------------------------------
__global__ __launch_bounds__(NT, 1) void qcnn_main(const float* __restrict__ x,
                                                   const float* __restrict__ bias,
                                                   float* __restrict__ out)
{
    __shared__ float sred[32][NCLS];

    const int rg   = blockIdx.x >> 1;        // row pair index
    const int h    = blockIdx.x & 1;         // window half
    const int tid  = threadIdx.x;
    const int lane = tid & 31;
    const int tp   = tid & 511;              // thread-in-half, 0..511
    const int row  = rg * 2 + (tid >> 9);    // warps 0-15: row A, 16-31: row B

    // ---- x loads + cos
    const float* xr = x + (size_t)row * OLP * 2;
    const float4* xr4 = (const float4*)xr;
    float4 v0 = xr4[1024 * h + 2 * tp];          // pairs 2048h+4tp, +1
    float4 v1 = xr4[1024 * h + 2 * tp + 1];      // pairs 2048h+4tp+2, +3

    float nx = __shfl_down_sync(0xFFFFFFFFu, v0.x, 1);
    float ny = __shfl_down_sync(0xFFFFFFFFu, v0.y, 1);
    if (lane == 31) {
        int wend = HWIN * h + 4 * tp + 4;                   // next pair index
        int off = (wend >= OLP) ? 0 : 2 * wend;             // clamp pad (w=0 there)
        float2 nb = *(const float2*)(xr + off);
        nx = nb.x; ny = nb.y;
    }

    float s1_0 = __cosf(v0.y);
    float s1_1 = __cosf(v0.w), h1 = __cosf(v0.z) * s1_1;
    float s1_2 = __cosf(v1.y), h2 = __cosf(v1.x) * s1_2;
    float s1_3 = __cosf(v1.w), h3 = __cosf(v1.z) * s1_3;
    float h4   = __cosf(nx)   * __cosf(ny);
    float g0 = s1_0 * h1;
    float g1 = s1_1 * h2;
    float g2 = s1_2 * h3;
    float g3 = s1_3 * h4;             // padded window 4095 has zero weight

    // ---- dot with folded weights: 10 coalesced LDG.128 (MLP=10; the second
    // row's warps hit L1 on the lines the first row's warps already pulled)
    const float4* Wp4 = (const float4*)d_Wp;
    float acc[NCLS];
#pragma unroll
    for (int j = 0; j < NCLS; ++j) {
        float4 w = Wp4[j * (OLP / 4) + 512 * h + tp];
        float a;
        a = g0 * w.x;
        a = fmaf(g1, w.y, a);
        a = fmaf(g2, w.z, a);
        a = fmaf(g3, w.w, a);
        acc[j] = a;
    }

    // ---- per-row reduce (16 warps each)
#pragma unroll
    for (int j = 0; j < NCLS; ++j) {
#pragma unroll
        for (int off = 16; off; off >>= 1)
            acc[j] += __shfl_xor_sync(0xFFFFFFFFu, acc[j], off);
    }
    const int warp = tid >> 5;
    if (lane == 0) {
#pragma unroll
        for (int j = 0; j < NCLS; ++j) sred[warp][j] = acc[j];
    }
    __syncthreads();

    // ---- half-row partial -> gmem combine; last half does the softmax.
    // Warp 0 finishes row A, warp 16 finishes row B (concurrently).
    if ((tid & 511) < 32) {
        const int wbase = (tid >> 9) * 16;
        float part = 0.0f;
        if (lane < NCLS) {
#pragma unroll
            for (int w = 0; w < 16; ++w) part += sred[wbase + w][lane];
            atomicAdd(&d_logits[row * NCLS + lane], part);
        }
        __threadfence();
        int isLast = 0;
        if (lane == 0) isLast = (atomicAdd(&d_tick[row], 1) == 1);
        isLast = __shfl_sync(0xFFFFFFFFu, isLast, 0);
        if (isLast) {
            float logit = -CUDART_INF_F;
            if (lane < NCLS)     // atomic read => L2-coherent combined value
                logit = atomicAdd(&d_logits[row * NCLS + lane], 0.0f) + bias[lane];
            float mx = logit;
#pragma unroll
            for (int off = 16; off; off >>= 1)
                mx = fmaxf(mx, __shfl_xor_sync(0xFFFFFFFFu, mx, off));
            float e = (lane < NCLS) ? __expf(logit - mx) : 0.0f;
            float s = e;
#pragma unroll
            for (int off = 16; off; off >>= 1)
                s += __shfl_xor_sync(0xFFFFFFFFu, s, off);
            if (lane < NCLS) {
                out[row * NCLS + lane] = e / s;
                d_logits[row * NCLS + lane] = 0.0f;   // self-clean for replay
            }
            if (lane == 0) d_tick[row] = 0;
        }
    }
}

// Inputs (metadata order): inputs(128*4096*2 f32), params(8 f32),
//                          W(8190*10 f32), b(10 f32). Output: (128*10) f32.
extern "C" void kernel_launch(void* const* d_in, const int* in_sizes, int n_in,
                              void* d_out, int out_size)
{
    const float* inputs = (const float*)d_in[0];
    const float* params = (const float*)d_in[1];
    const float* W      = (const float*)d_in[2];
    const float* bias   = (const float*)d_in[3];
    float* out          = (float*)d_out;

    qcnn_prep<<<32, 256>>>(params, W);
    qcnn_main<<<B_SZ, NT>>>(inputs, bias, out);
}

// round 14
// speedup vs baseline: 1.9938x; 1.0186x over previous
#include <cuda_runtime.h>
#include <math_constants.h>
#include <cstdint>

// Problem: B=128, L=4096, FILTER_SIZE=2, N_QUBITS=4, 10 classes.
// Analytic reduction: expval_k(b,ol) = K_k * g(b,ol),
//   K_k = cos(p_k1)cos(p_k2)cos(p_k3)   (CNOT ring conjugates Z0 -> Z1Z2Z3)
//   g   = cos(x[ol,1]) * cos(x[ol+1,0]) * cos(x[ol+1,1])
// logits[j] = bias[j] + sum_ol g(ol)*(K0*W[2ol,j]+K1*W[2ol+1,j]); softmax.
//
// R4 structure (proven fastest) + PDL: main launches while prep still runs,
// front-runs its x-load/cos phase, and gates only the Wp dot on prep's
// completion via cudaGridDependencySynchronize().
#define OLP    4096
#define NCLS   10
#define B_SZ   128
#define NT     1024
#define NWARP  (NT / 32)
#define W_F4   20475          // float4 count of W (8190*10 floats)

// Folded, TRANSPOSED weights d_Wp[j*OLP + ol]; column 4095 is zero (pad).
__device__ __align__(16) float d_Wp[NCLS * OLP];

// ---------------------------------------------------------------------------
// Prep: fold+transpose W into d_Wp. 32 blocks x 256 threads.
// Triggers programmatic launch completion as soon as its stores are fenced.
// ---------------------------------------------------------------------------
__global__ __launch_bounds__(256) void qcnn_prep(const float* __restrict__ params,
                                                 const float* __restrict__ W)
{
    __shared__ float sw[2560];
    const int bid = blockIdx.x, tid = threadIdx.x;

    const float4* w4 = (const float4*)W;
    const int f4base = bid * 640;
#pragma unroll
    for (int k = 0; k < 3; ++k) {
        int li = tid + k * 256;
        if (li < 640) {
            int gi = f4base + li;
            float4 v = (gi < W_F4) ? w4[gi] : make_float4(0.f, 0.f, 0.f, 0.f);
            *(float4*)&sw[4 * li] = v;
        }
    }
    __syncthreads();

    if (tid < 128) {
        float K0 = __cosf(params[1]) * __cosf(params[2]) * __cosf(params[3]);
        float K1 = __cosf(params[5]) * __cosf(params[6]) * __cosf(params[7]);
        int ol = bid * 128 + tid;
        const float* r = &sw[20 * tid];          // rows 2ol, 2ol+1 (10 f each)
#pragma unroll
        for (int j = 0; j < NCLS; ++j)
            d_Wp[j * OLP + ol] = fmaf(K1, r[10 + j], K0 * r[j]);
        __threadfence();                         // publish before trigger
    }
    __syncthreads();
    cudaTriggerProgrammaticLaunchCompletion();   // all blocks -> event fires
}

// ---------------------------------------------------------------------------
// Main (R4-identical math): one block (1024 threads) per batch row.
// Phase 1 (x loads, shuffle, cos) runs concurrently with prep; the
// grid-dependency sync gates only the Wp reads.
// ---------------------------------------------------------------------------
__global__ __launch_bounds__(NT, 1) void qcnn_main(const float* __restrict__ x,
                                                   const float* __restrict__ bias,
                                                   float* __restrict__ out)
{
    __shared__ float sred[NWARP][NCLS];

    const int b   = blockIdx.x;
    const int tid = threadIdx.x;

    // ---- phase 1: x pairs 4t..4t+3 (two float4 per thread)
    const float* xr = x + (size_t)b * OLP * 2;
    const float4* row4 = (const float4*)xr;
    float4 v0 = row4[2 * tid];
    float4 v1 = row4[2 * tid + 1];

    // neighbor pair 4t+4 via shuffle; lane 31 from gmem
    float nx = __shfl_down_sync(0xFFFFFFFFu, v0.x, 1);
    float ny = __shfl_down_sync(0xFFFFFFFFu, v0.y, 1);
    if ((tid & 31) == 31) {
        int off = (tid == 1023) ? 0 : 8 * tid + 8;   // tid=1023: value unused
        float2 nb = *(const float2*)(xr + off);
        nx = nb.x; ny = nb.y;
    }

    // s1[i]=cos(x1), h[i]=cos(x0)*s1[i];  g_k = s1[k]*h[k+1]
    float s1_0 = __cosf(v0.y);
    float s1_1 = __cosf(v0.w), h1 = __cosf(v0.z) * s1_1;
    float s1_2 = __cosf(v1.y), h2 = __cosf(v1.x) * s1_2;
    float s1_3 = __cosf(v1.w), h3 = __cosf(v1.z) * s1_3;
    float h4   = __cosf(nx)   * __cosf(ny);
    float g0 = s1_0 * h1;
    float g1 = s1_1 * h2;
    float g2 = s1_2 * h3;
    float g3 = (tid == 1023) ? 0.0f : s1_3 * h4;    // window 4095 is padding

    // ---- gate on prep's d_Wp being published (overlapped until here)
    cudaGridDependencySynchronize();

    // ---- dot with folded weights: 10 coalesced, L2-hot LDG.128
    const float4* Wp4 = (const float4*)d_Wp;
    float acc[NCLS];
#pragma unroll
    for (int j = 0; j < NCLS; ++j) {
        float4 w = Wp4[j * (OLP / 4) + tid];
        float a;
        a = g0 * w.x;
        a = fmaf(g1, w.y, a);
        a = fmaf(g2, w.z, a);
        a = fmaf(g3, w.w, a);
        acc[j] = a;
    }

    // ---- reduce 1024 threads -> 10 logits
#pragma unroll
    for (int j = 0; j < NCLS; ++j) {
#pragma unroll
        for (int off = 16; off; off >>= 1)
            acc[j] += __shfl_xor_sync(0xFFFFFFFFu, acc[j], off);
    }
    const int warp = tid >> 5, lane = tid & 31;
    if (lane == 0) {
#pragma unroll
        for (int j = 0; j < NCLS; ++j) sred[warp][j] = acc[j];
    }
    __syncthreads();

    // ---- final reduce + softmax in warp 0 (lanes 0..9 own one class)
    if (tid < 32) {
        float logit = -CUDART_INF_F;
        if (tid < NCLS) {
            logit = bias[tid];
#pragma unroll
            for (int w = 0; w < NWARP; ++w) logit += sred[w][tid];
        }
        float mx = logit;
#pragma unroll
        for (int off = 16; off; off >>= 1)
            mx = fmaxf(mx, __shfl_xor_sync(0xFFFFFFFFu, mx, off));
        float e = (tid < NCLS) ? __expf(logit - mx) : 0.0f;
        float s = e;
#pragma unroll
        for (int off = 16; off; off >>= 1)
            s += __shfl_xor_sync(0xFFFFFFFFu, s, off);
        if (tid < NCLS) out[b * NCLS + tid] = e / s;
    }
}

// Inputs (metadata order): inputs(128*4096*2 f32), params(8 f32),
//                          W(8190*10 f32), b(10 f32). Output: (128*10) f32.
extern "C" void kernel_launch(void* const* d_in, const int* in_sizes, int n_in,
                              void* d_out, int out_size)
{
    const float* inputs = (const float*)d_in[0];
    const float* params = (const float*)d_in[1];
    const float* W      = (const float*)d_in[2];
    const float* bias   = (const float*)d_in[3];
    float* out          = (float*)d_out;

    qcnn_prep<<<32, 256>>>(params, W);

    // Launch main with PDL so it overlaps prep; it self-gates on d_Wp.
    cudaLaunchAttribute attr[1];
    attr[0].id = cudaLaunchAttributeProgrammaticStreamSerialization;
    attr[0].val.programmaticStreamSerializationAllowed = 1;

    cudaLaunchConfig_t cfg = {};
    cfg.gridDim  = dim3(B_SZ);
    cfg.blockDim = dim3(NT);
    cfg.dynamicSmemBytes = 0;
    cfg.stream   = 0;
    cfg.attrs    = attr;
    cfg.numAttrs = 1;
    cudaLaunchKernelEx(&cfg, qcnn_main, inputs, bias, out);
}

// round 15
// speedup vs baseline: 2.0510x; 1.0287x over previous
#include <cuda_runtime.h>
#include <math_constants.h>
#include <cstdint>

// Problem: B=128, L=4096, FILTER_SIZE=2, N_QUBITS=4, 10 classes.
// Analytic reduction: expval_k(b,ol) = K_k * g(b,ol),
//   K_k = cos(p_k1)cos(p_k2)cos(p_k3)   (CNOT ring conjugates Z0 -> Z1Z2Z3)
//   g   = cos(x[ol,1]) * cos(x[ol+1,0]) * cos(x[ol+1,1])
// logits[j] = bias[j] + sum_ol g(ol)*(K0*W[2ol,j]+K1*W[2ol+1,j]); softmax.
//
// R4 structure (proven fastest) with the 50-SHFL/thread butterfly reduce
// replaced by a smem transpose reduce (10 STS + 10 class-warps of LDS.128).
#define OLP    4096
#define NCLS   10
#define B_SZ   128
#define NT     1024
#define W_F4   20475          // float4 count of W (8190*10 floats)

// Folded, TRANSPOSED weights d_Wp[j*OLP + ol]; column 4095 is zero (pad).
__device__ __align__(16) float d_Wp[NCLS * OLP];

// ---------------------------------------------------------------------------
// Prep: fold+transpose W into d_Wp. 32 blocks x 256 threads (R4-proven).
// ---------------------------------------------------------------------------
__global__ __launch_bounds__(256) void qcnn_prep(const float* __restrict__ params,
                                                 const float* __restrict__ W)
{
    __shared__ float sw[2560];
    const int bid = blockIdx.x, tid = threadIdx.x;

    const float4* w4 = (const float4*)W;
    const int f4base = bid * 640;
#pragma unroll
    for (int k = 0; k < 3; ++k) {
        int li = tid + k * 256;
        if (li < 640) {
            int gi = f4base + li;
            float4 v = (gi < W_F4) ? w4[gi] : make_float4(0.f, 0.f, 0.f, 0.f);
            *(float4*)&sw[4 * li] = v;
        }
    }
    __syncthreads();

    if (tid < 128) {
        float K0 = __cosf(params[1]) * __cosf(params[2]) * __cosf(params[3]);
        float K1 = __cosf(params[5]) * __cosf(params[6]) * __cosf(params[7]);
        int ol = bid * 128 + tid;
        const float* r = &sw[20 * tid];          // rows 2ol, 2ol+1 (10 f each)
#pragma unroll
        for (int j = 0; j < NCLS; ++j)
            d_Wp[j * OLP + ol] = fmaf(K1, r[10 + j], K0 * r[j]);
    }
}

// ---------------------------------------------------------------------------
// Main: one block (1024 threads) per batch row, 4 windows per thread.
// Phase 1/dot identical to R4; reduce is a smem transpose reduce.
// ---------------------------------------------------------------------------
__global__ __launch_bounds__(NT, 1) void qcnn_main(const float* __restrict__ x,
                                                   const float* __restrict__ bias,
                                                   float* __restrict__ out)
{
    __shared__ __align__(16) float sacc[NCLS][NT];   // 40 KB transpose buffer
    __shared__ float stot[NCLS];

    const int b    = blockIdx.x;
    const int tid  = threadIdx.x;
    const int lane = tid & 31;
    const int warp = tid >> 5;

    // ---- phase 1: x pairs 4t..4t+3 (two float4 per thread)
    const float* xr = x + (size_t)b * OLP * 2;
    const float4* row4 = (const float4*)xr;
    float4 v0 = row4[2 * tid];
    float4 v1 = row4[2 * tid + 1];

    // neighbor pair 4t+4 via shuffle; lane 31 from gmem
    float nx = __shfl_down_sync(0xFFFFFFFFu, v0.x, 1);
    float ny = __shfl_down_sync(0xFFFFFFFFu, v0.y, 1);
    if (lane == 31) {
        int off = (tid == NT - 1) ? 0 : 8 * tid + 8;   // tid=1023: value unused
        float2 nb = *(const float2*)(xr + off);
        nx = nb.x; ny = nb.y;
    }

    // s1[i]=cos(x1), h[i]=cos(x0)*s1[i];  g_k = s1[k]*h[k+1]
    float s1_0 = __cosf(v0.y);
    float s1_1 = __cosf(v0.w), h1 = __cosf(v0.z) * s1_1;
    float s1_2 = __cosf(v1.y), h2 = __cosf(v1.x) * s1_2;
    float s1_3 = __cosf(v1.w), h3 = __cosf(v1.z) * s1_3;
    float h4   = __cosf(nx)   * __cosf(ny);
    float g0 = s1_0 * h1;
    float g1 = s1_1 * h2;
    float g2 = s1_2 * h3;
    float g3 = (tid == NT - 1) ? 0.0f : s1_3 * h4;   // window 4095 is padding

    // ---- dot with folded weights: 10 coalesced, L2-hot LDG.128 (MLP=10)
    const float4* Wp4 = (const float4*)d_Wp;
#pragma unroll
    for (int j = 0; j < NCLS; ++j) {
        float4 w = Wp4[j * (OLP / 4) + tid];
        float a;
        a = g0 * w.x;
        a = fmaf(g1, w.y, a);
        a = fmaf(g2, w.z, a);
        a = fmaf(g3, w.w, a);
        sacc[j][tid] = a;                  // conflict-free STS.32
    }
    __syncthreads();

    // ---- transpose reduce: warp j sums class j's 1024 partials
    if (warp < NCLS) {
        const float4* p = (const float4*)&sacc[warp][0];   // 256 float4
        float4 s = p[lane];
#pragma unroll
        for (int k = 1; k < 8; ++k) {      // 8 conflict-free LDS.128 total
            float4 q = p[lane + 32 * k];
            s.x += q.x; s.y += q.y; s.z += q.z; s.w += q.w;
        }
        float v = (s.x + s.y) + (s.z + s.w);
#pragma unroll
        for (int off = 16; off; off >>= 1)
            v += __shfl_xor_sync(0xFFFFFFFFu, v, off);
        if (lane == 0) stot[warp] = v;
    }
    __syncthreads();

    // ---- softmax in warp 0 (lanes 0..9 own one class)
    if (tid < 32) {
        float logit = (tid < NCLS) ? (stot[tid] + bias[tid]) : -CUDART_INF_F;
        float mx = logit;
#pragma unroll
        for (int off = 16; off; off >>= 1)
            mx = fmaxf(mx, __shfl_xor_sync(0xFFFFFFFFu, mx, off));
        float e = (tid < NCLS) ? __expf(logit - mx) : 0.0f;
        float s = e;
#pragma unroll
        for (int off = 16; off; off >>= 1)
            s += __shfl_xor_sync(0xFFFFFFFFu, s, off);
        if (tid < NCLS) out[b * NCLS + tid] = e / s;
    }
}

// Inputs (metadata order): inputs(128*4096*2 f32), params(8 f32),
//                          W(8190*10 f32), b(10 f32). Output: (128*10) f32.
extern "C" void kernel_launch(void* const* d_in, const int* in_sizes, int n_in,
                              void* d_out, int out_size)
{
    const float* inputs = (const float*)d_in[0];
    const float* params = (const float*)d_in[1];
    const float* W      = (const float*)d_in[2];
    const float* bias   = (const float*)d_in[3];
    float* out          = (float*)d_out;

    qcnn_prep<<<32, 256>>>(params, W);
    qcnn_main<<<B_SZ, NT>>>(inputs, bias, out);
}